// round 12
// baseline (speedup 1.0000x reference)
#include <cuda_runtime.h>
#include <cuda_bf16.h>
#include <cstdint>

#define BATCH 32
#define CIN   1024
#define PMID  256
#define HW    784

// Pre-split operands (bf16 hi/lo)
__device__ uint16_t g_xh [BATCH * CIN * HW],  g_xl [BATCH * CIN * HW];
__device__ uint16_t g_w1h[PMID * CIN],        g_w1l[PMID * CIN];
__device__ uint16_t g_w3h[CIN * PMID],        g_w3l[CIN * PMID];
__device__ uint16_t g_wdh[9 * PMID * PMID],   g_wdl[9 * PMID * PMID];   // [tap][q][p]
__device__ uint16_t g_y1h[BATCH * PMID * HW], g_y1l[BATCH * PMID * HW];
// im2col: 9 tap-shifted shuffled copies, compact [tap][b*PMID+p][784]
__device__ uint16_t g_ysth[9 * BATCH * PMID * HW], g_ystl[9 * BATCH * PMID * HW];
__device__ uint16_t g_y2h[BATCH * PMID * HW], g_y2l[BATCH * PMID * HW];

// SMEM: 3 stages. A rows 80B (k32+8pad), B rows 240B (n112+8pad)
// AH: 3x10240 @0 ; AL: 3x10240 @30720 ; BH: 3x7680 @61440 ; BL: 3x7680 @84480
#define ASTRIDE 10240u
#define BSTRIDE 7680u
#define OFF_AL  30720u
#define OFF_BH  61440u
#define OFF_BL  84480u
#define SMEM_BYTES 107520

// ---------------------------------------------------------------------------
__device__ __forceinline__ void split_bf(float v, uint16_t& h, uint16_t& l) {
    __nv_bfloat16 bh = __float2bfloat16(v);
    float r = v - __bfloat162float(bh);
    h = __bfloat16_as_ushort(bh);
    l = __bfloat16_as_ushort(__float2bfloat16(r));
}
__device__ __forceinline__ uint32_t pack2(uint16_t a, uint16_t b) {
    return (uint32_t)a | ((uint32_t)b << 16);
}
__device__ __forceinline__ uint32_t smem_u32(const void* p) {
    uint32_t a;
    asm("{ .reg .u64 t; cvta.to.shared.u64 t, %1; cvt.u32.u64 %0, t; }" : "=r"(a) : "l"(p));
    return a;
}
__device__ __forceinline__ void cp16(uint32_t d, const void* s) {
    asm volatile("cp.async.ca.shared.global [%0], [%1], 16;" :: "r"(d), "l"(s));
}
#define CP_COMMIT() asm volatile("cp.async.commit_group;" ::: "memory")
#define CP_WAIT0()  asm volatile("cp.async.wait_group 0;" ::: "memory")
#define CP_WAIT1()  asm volatile("cp.async.wait_group 1;" ::: "memory")

__device__ __forceinline__ void ldm_x4(uint32_t* r, uint32_t a) {
    asm volatile("ldmatrix.sync.aligned.m8n8.x4.shared.b16 {%0,%1,%2,%3}, [%4];"
        : "=r"(r[0]), "=r"(r[1]), "=r"(r[2]), "=r"(r[3]) : "r"(a));
}
__device__ __forceinline__ void ldm_x4t(uint32_t* r, uint32_t a) {
    asm volatile("ldmatrix.sync.aligned.m8n8.x4.trans.shared.b16 {%0,%1,%2,%3}, [%4];"
        : "=r"(r[0]), "=r"(r[1]), "=r"(r[2]), "=r"(r[3]) : "r"(a));
}
__device__ __forceinline__ void ldm_x2t(uint32_t* r, uint32_t a) {
    asm volatile("ldmatrix.sync.aligned.m8n8.x2.trans.shared.b16 {%0,%1}, [%2];"
        : "=r"(r[0]), "=r"(r[1]) : "r"(a));
}
__device__ __forceinline__ void mma_bf(float* d, const uint32_t* a,
                                       uint32_t b0, uint32_t b1) {
    asm volatile(
        "mma.sync.aligned.m16n8k16.row.col.f32.bf16.bf16.f32 "
        "{%0,%1,%2,%3}, {%4,%5,%6,%7}, {%8,%9}, {%0,%1,%2,%3};"
        : "+f"(d[0]), "+f"(d[1]), "+f"(d[2]), "+f"(d[3])
        : "r"(a[0]), "r"(a[1]), "r"(a[2]), "r"(a[3]), "r"(b0), "r"(b1));
}

// One BK=32 chunk; warp tile 32(M) x 56(N); split-bf16 x3 (hh, lh, hl).
__device__ __forceinline__ void compute_chunk32(
    uint32_t ah, uint32_t al, uint32_t bh, uint32_t bl,
    uint32_t aoff0, uint32_t aoff1, uint32_t boff, uint32_t boff6,
    float acc[2][7][4]) {
    #pragma unroll
    for (int s = 0; s < 2; s++) {
        uint32_t a_h[2][4], a_l[2][4];
        ldm_x4(a_h[0], ah + aoff0 + s * 32);
        ldm_x4(a_h[1], ah + aoff1 + s * 32);
        ldm_x4(a_l[0], al + aoff0 + s * 32);
        ldm_x4(a_l[1], al + aoff1 + s * 32);
        const uint32_t bstep = s * 3840;   // 16 k-rows x 240B
        #pragma unroll
        for (int j2 = 0; j2 < 3; j2++) {
            uint32_t rh[4], rl[4];
            ldm_x4t(rh, bh + boff + bstep + j2 * 32);
            ldm_x4t(rl, bl + boff + bstep + j2 * 32);
            #pragma unroll
            for (int jj = 0; jj < 2; jj++) {
                const int j = 2 * j2 + jj;
                #pragma unroll
                for (int i = 0; i < 2; i++) {
                    mma_bf(acc[i][j], a_h[i], rh[2*jj], rh[2*jj+1]);
                    mma_bf(acc[i][j], a_l[i], rh[2*jj], rh[2*jj+1]);
                    mma_bf(acc[i][j], a_h[i], rl[2*jj], rl[2*jj+1]);
                }
            }
        }
        {
            uint32_t rh[2], rl[2];
            ldm_x2t(rh, bh + boff6 + bstep);
            ldm_x2t(rl, bl + boff6 + bstep);
            #pragma unroll
            for (int i = 0; i < 2; i++) {
                mma_bf(acc[i][6], a_h[i], rh[0], rh[1]);
                mma_bf(acc[i][6], a_l[i], rh[0], rh[1]);
                mma_bf(acc[i][6], a_h[i], rl[0], rl[1]);
            }
        }
    }
}

// ---------------------------------------------------------------------------
// Prep kernels
// ---------------------------------------------------------------------------
__global__ __launch_bounds__(256) void p_split(const float* __restrict__ in,
                                               uint16_t* __restrict__ oh,
                                               uint16_t* __restrict__ ol, int n4) {
    int i = blockIdx.x * 256 + threadIdx.x;
    if (i >= n4) return;
    float4 v = ((const float4*)in)[i];
    uint16_t h0,l0,h1,l1,h2,l2,h3,l3;
    split_bf(v.x,h0,l0); split_bf(v.y,h1,l1); split_bf(v.z,h2,l2); split_bf(v.w,h3,l3);
    ((uint2*)oh)[i] = make_uint2(pack2(h0,h1), pack2(h2,h3));
    ((uint2*)ol)[i] = make_uint2(pack2(l0,l1), pack2(l2,l3));
}

__global__ __launch_bounds__(256) void p_wd(const float* __restrict__ wd) {
    int e = blockIdx.x * 256 + threadIdx.x;   // e = tap*65536 + q*256 + p
    int p = e & 255, q = (e >> 8) & 255, tap = e >> 16;
    float v = wd[q * 2304 + p * 9 + tap];
    uint16_t h, l; split_bf(v, h, l);
    g_wdh[e] = h; g_wdl[e] = l;
}

// shuffle + im2col: for each (b,p) produce 9 tap-shifted rows of 784
__global__ __launch_bounds__(256) void p_shuf9(const int* __restrict__ perm) {
    __shared__ int sperm[HW];
    __shared__ uint16_t syh[HW], syl[HW];
    const int bp = blockIdx.x, p = bp & (PMID - 1);
    const int tid = threadIdx.x;
    for (int t = tid; t < HW; t += 256) {
        sperm[t] = perm[(size_t)p * HW + t];
        syh[t] = g_y1h[(size_t)bp * HW + t];
        syl[t] = g_y1l[(size_t)bp * HW + t];
    }
    __syncthreads();
    #pragma unroll
    for (int tap = 0; tap < 9; tap++) {
        const int dy = tap / 3 - 1, dx = tap % 3 - 1;
        uint16_t* dh = g_ysth + ((size_t)tap * (BATCH * PMID) + bp) * HW;
        uint16_t* dl = g_ystl + ((size_t)tap * (BATCH * PMID) + bp) * HW;
        for (int hw = tid; hw < HW; hw += 256) {
            int h = hw / 28 + dy, w = hw % 28 + dx;
            uint16_t vh = 0, vl = 0;
            if ((unsigned)h < 28u && (unsigned)w < 28u) {
                int j = sperm[h * 28 + w];
                vh = syh[j]; vl = syl[j];
            }
            dh[hw] = vh; dl[hw] = vl;
        }
    }
}

// ---------------------------------------------------------------------------
// Common per-kernel decls: 256 threads, 8 warps = 4(wm) x 2(wn), warp 32x56.
// ---------------------------------------------------------------------------
#define PIPE_DECLS()                                                           \
    extern __shared__ uint16_t sm[];                                           \
    const uint32_t sb = smem_u32(sm);                                          \
    const int tid = threadIdx.x, lane = tid & 31, warp = tid >> 5;             \
    const int wm = warp >> 1, wn = warp & 1;                                   \
    const int ar = tid >> 1, ac = (tid & 1) << 4;                              \
    const int bkc = tid / 7, bch = (tid % 7) << 4;                             \
    const uint32_t aoff0 = ((wm * 32 + (lane & 15)) * 40 + ((lane >> 4) << 3)) * 2;      \
    const uint32_t aoff1 = ((wm * 32 + 16 + (lane & 15)) * 40 + ((lane >> 4) << 3)) * 2; \
    const uint32_t boff  = ((lane & 15) * 120 + wn * 56 + ((lane >> 4) << 3)) * 2;       \
    const uint32_t boff6 = ((lane & 15) * 120 + wn * 56 + 48) * 2;             \
    float acc[2][7][4] = {};

// ---------------------------------------------------------------------------
// K1: y1 = relu(w1 @ x). M=256, K=1024, N=784. Tile 128x112, BK=32, 256 thr.
// ---------------------------------------------------------------------------
__global__ __launch_bounds__(256, 2) void k1() {
    const int b = blockIdx.z, m0 = blockIdx.y * 128, n0 = blockIdx.x * 112;
    const uint16_t* xh = g_xh + (size_t)b * CIN * HW;
    const uint16_t* xl = g_xl + (size_t)b * CIN * HW;
    PIPE_DECLS();

#define K1_ISSUE(k0, st) do {                                                  \
    cp16(sb + (st) * ASTRIDE + (ar * 40 + ac) * 2,                             \
         g_w1h + (size_t)(m0 + ar) * CIN + (k0) + ac);                         \
    cp16(sb + (st) * ASTRIDE + (ar * 40 + ac + 8) * 2,                         \
         g_w1h + (size_t)(m0 + ar) * CIN + (k0) + ac + 8);                     \
    cp16(sb + OFF_AL + (st) * ASTRIDE + (ar * 40 + ac) * 2,                    \
         g_w1l + (size_t)(m0 + ar) * CIN + (k0) + ac);                         \
    cp16(sb + OFF_AL + (st) * ASTRIDE + (ar * 40 + ac + 8) * 2,                \
         g_w1l + (size_t)(m0 + ar) * CIN + (k0) + ac + 8);                     \
    if (tid < 224) {                                                           \
        cp16(sb + OFF_BH + (st) * BSTRIDE + (bkc * 120 + bch) * 2,             \
             xh + (size_t)((k0) + bkc) * HW + n0 + bch);                       \
        cp16(sb + OFF_BH + (st) * BSTRIDE + (bkc * 120 + bch + 8) * 2,         \
             xh + (size_t)((k0) + bkc) * HW + n0 + bch + 8);                   \
        cp16(sb + OFF_BL + (st) * BSTRIDE + (bkc * 120 + bch) * 2,             \
             xl + (size_t)((k0) + bkc) * HW + n0 + bch);                       \
        cp16(sb + OFF_BL + (st) * BSTRIDE + (bkc * 120 + bch + 8) * 2,         \
             xl + (size_t)((k0) + bkc) * HW + n0 + bch + 8);                   \
    }                                                                          \
    CP_COMMIT(); } while (0)

    K1_ISSUE(0, 0); K1_ISSUE(32, 1);
    for (int c = 0; c < 32; c++) {
        const int s = c % 3;
        if (c + 2 < 32) CP_WAIT1(); else CP_WAIT0();
        __syncthreads();
        if (c + 2 < 32) K1_ISSUE((c + 2) * 32, (c + 2) % 3);
        compute_chunk32(sb + s * ASTRIDE, sb + OFF_AL + s * ASTRIDE,
                        sb + OFF_BH + s * BSTRIDE, sb + OFF_BL + s * BSTRIDE,
                        aoff0, aoff1, boff, boff6, acc);
    }
#undef K1_ISSUE

    const int r0 = lane >> 2, c2 = (lane & 3) << 1;
    #pragma unroll
    for (int i = 0; i < 2; i++)
        #pragma unroll
        for (int rp = 0; rp < 2; rp++) {
            int m = m0 + wm * 32 + i * 16 + r0 + rp * 8;
            size_t base = (size_t)(b * PMID + m) * HW + n0;
            #pragma unroll
            for (int j = 0; j < 7; j++) {
                int col = wn * 56 + j * 8 + c2;
                float v0 = fmaxf(acc[i][j][rp * 2], 0.f);
                float v1 = fmaxf(acc[i][j][rp * 2 + 1], 0.f);
                uint16_t h0,l0,h1,l1; split_bf(v0,h0,l0); split_bf(v1,h1,l1);
                *(uint32_t*)&g_y1h[base + col] = pack2(h0, h1);
                *(uint32_t*)&g_y1l[base + col] = pack2(l0, l1);
            }
        }
}

// ---------------------------------------------------------------------------
// K3: y2 = relu(conv3x3). 72 chunks = 9 taps x 8 p-chunks, pure cp.async GEMM.
// ---------------------------------------------------------------------------
__global__ __launch_bounds__(256, 2) void k3() {
    const int b = blockIdx.z, q0 = blockIdx.y * 128, n0 = blockIdx.x * 112;
    PIPE_DECLS();

#define K3_ISSUE(cc, st) do {                                                  \
    int tap_ = (cc) >> 3, p0_ = ((cc) & 7) << 5;                               \
    const uint16_t* wah = g_wdh + (size_t)tap_ * 65536 + (size_t)(q0 + ar) * 256 + p0_; \
    const uint16_t* wal = g_wdl + (size_t)tap_ * 65536 + (size_t)(q0 + ar) * 256 + p0_; \
    cp16(sb + (st) * ASTRIDE + (ar * 40 + ac) * 2,           wah + ac);        \
    cp16(sb + (st) * ASTRIDE + (ar * 40 + ac + 8) * 2,       wah + ac + 8);    \
    cp16(sb + OFF_AL + (st) * ASTRIDE + (ar * 40 + ac) * 2,     wal + ac);     \
    cp16(sb + OFF_AL + (st) * ASTRIDE + (ar * 40 + ac + 8) * 2, wal + ac + 8); \
    if (tid < 224) {                                                           \
        size_t brow = ((size_t)tap_ * (BATCH * PMID) + (size_t)b * PMID + p0_ + bkc) * HW + n0; \
        cp16(sb + OFF_BH + (st) * BSTRIDE + (bkc * 120 + bch) * 2,     g_ysth + brow + bch);     \
        cp16(sb + OFF_BH + (st) * BSTRIDE + (bkc * 120 + bch + 8) * 2, g_ysth + brow + bch + 8); \
        cp16(sb + OFF_BL + (st) * BSTRIDE + (bkc * 120 + bch) * 2,     g_ystl + brow + bch);     \
        cp16(sb + OFF_BL + (st) * BSTRIDE + (bkc * 120 + bch + 8) * 2, g_ystl + brow + bch + 8); \
    }                                                                          \
    CP_COMMIT(); } while (0)

    K3_ISSUE(0, 0); K3_ISSUE(1, 1);
    for (int c = 0; c < 72; c++) {
        const int s = c % 3;
        if (c + 2 < 72) CP_WAIT1(); else CP_WAIT0();
        __syncthreads();
        if (c + 2 < 72) K3_ISSUE(c + 2, (c + 2) % 3);
        compute_chunk32(sb + s * ASTRIDE, sb + OFF_AL + s * ASTRIDE,
                        sb + OFF_BH + s * BSTRIDE, sb + OFF_BL + s * BSTRIDE,
                        aoff0, aoff1, boff, boff6, acc);
    }
#undef K3_ISSUE

    const int r0 = lane >> 2, c2 = (lane & 3) << 1;
    #pragma unroll
    for (int i = 0; i < 2; i++)
        #pragma unroll
        for (int rp = 0; rp < 2; rp++) {
            int q = q0 + wm * 32 + i * 16 + r0 + rp * 8;
            size_t base = (size_t)(b * PMID + q) * HW + n0;
            #pragma unroll
            for (int j = 0; j < 7; j++) {
                int col = wn * 56 + j * 8 + c2;
                float v0 = fmaxf(acc[i][j][rp * 2], 0.f);
                float v1 = fmaxf(acc[i][j][rp * 2 + 1], 0.f);
                uint16_t h0,l0,h1,l1; split_bf(v0,h0,l0); split_bf(v1,h1,l1);
                *(uint32_t*)&g_y2h[base + col] = pack2(h0, h1);
                *(uint32_t*)&g_y2l[base + col] = pack2(l0, l1);
            }
        }
}

// ---------------------------------------------------------------------------
// K4: out = relu(w3 @ y2 + shuffled residual). M=1024, K=256.
// ---------------------------------------------------------------------------
__global__ __launch_bounds__(256, 2) void k4(const float* __restrict__ x,
                                             const int* __restrict__ perm_res,
                                             float* __restrict__ out) {
    const int b = blockIdx.z, m0 = blockIdx.y * 128, n0 = blockIdx.x * 112;
    const uint16_t* yh = g_y2h + (size_t)b * PMID * HW;
    const uint16_t* yl = g_y2l + (size_t)b * PMID * HW;
    PIPE_DECLS();

#define K4_ISSUE(k0, st) do {                                                  \
    cp16(sb + (st) * ASTRIDE + (ar * 40 + ac) * 2,                             \
         g_w3h + (size_t)(m0 + ar) * PMID + (k0) + ac);                        \
    cp16(sb + (st) * ASTRIDE + (ar * 40 + ac + 8) * 2,                         \
         g_w3h + (size_t)(m0 + ar) * PMID + (k0) + ac + 8);                    \
    cp16(sb + OFF_AL + (st) * ASTRIDE + (ar * 40 + ac) * 2,                    \
         g_w3l + (size_t)(m0 + ar) * PMID + (k0) + ac);                        \
    cp16(sb + OFF_AL + (st) * ASTRIDE + (ar * 40 + ac + 8) * 2,                \
         g_w3l + (size_t)(m0 + ar) * PMID + (k0) + ac + 8);                    \
    if (tid < 224) {                                                           \
        cp16(sb + OFF_BH + (st) * BSTRIDE + (bkc * 120 + bch) * 2,             \
             yh + (size_t)((k0) + bkc) * HW + n0 + bch);                       \
        cp16(sb + OFF_BH + (st) * BSTRIDE + (bkc * 120 + bch + 8) * 2,         \
             yh + (size_t)((k0) + bkc) * HW + n0 + bch + 8);                   \
        cp16(sb + OFF_BL + (st) * BSTRIDE + (bkc * 120 + bch) * 2,             \
             yl + (size_t)((k0) + bkc) * HW + n0 + bch);                       \
        cp16(sb + OFF_BL + (st) * BSTRIDE + (bkc * 120 + bch + 8) * 2,         \
             yl + (size_t)((k0) + bkc) * HW + n0 + bch + 8);                   \
    }                                                                          \
    CP_COMMIT(); } while (0)

    K4_ISSUE(0, 0); K4_ISSUE(32, 1);
    for (int c = 0; c < 8; c++) {
        const int s = c % 3;
        if (c + 2 < 8) CP_WAIT1(); else CP_WAIT0();
        __syncthreads();
        if (c + 2 < 8) K4_ISSUE((c + 2) * 32, (c + 2) % 3);
        compute_chunk32(sb + s * ASTRIDE, sb + OFF_AL + s * ASTRIDE,
                        sb + OFF_BH + s * BSTRIDE, sb + OFF_BL + s * BSTRIDE,
                        aoff0, aoff1, boff, boff6, acc);
    }
#undef K4_ISSUE

    const int r0 = lane >> 2, c2 = (lane & 3) << 1;
    #pragma unroll
    for (int i = 0; i < 2; i++)
        #pragma unroll
        for (int rp = 0; rp < 2; rp++) {
            int m = m0 + wm * 32 + i * 16 + r0 + rp * 8;
            const int*   pr  = perm_res + (size_t)m * HW + n0;
            const float* xr  = x   + (size_t)(b * CIN + m) * HW;
            float*       dst = out + (size_t)(b * CIN + m) * HW + n0;
            #pragma unroll
            for (int j = 0; j < 7; j++) {
                int col = wn * 56 + j * 8 + c2;
                float v0 = acc[i][j][rp * 2]     + xr[pr[col]];
                float v1 = acc[i][j][rp * 2 + 1] + xr[pr[col + 1]];
                *(float2*)&dst[col] = make_float2(fmaxf(v0, 0.f), fmaxf(v1, 0.f));
            }
        }
}

// ---------------------------------------------------------------------------
extern "C" void kernel_launch(void* const* d_in, const int* in_sizes, int n_in,
                              void* d_out, int out_size) {
    const float* x        = (const float*)d_in[0];
    const float* w1       = (const float*)d_in[1];
    const float* wd       = (const float*)d_in[2];
    const float* w3       = (const float*)d_in[3];
    const int*   perm_d   = (const int*)d_in[4];
    const int*   perm_res = (const int*)d_in[5];
    float* out = (float*)d_out;
    (void)in_sizes; (void)n_in; (void)out_size;

    static bool attr_done = false;
    if (!attr_done) {
        cudaFuncSetAttribute(k1, cudaFuncAttributeMaxDynamicSharedMemorySize, SMEM_BYTES);
        cudaFuncSetAttribute(k3, cudaFuncAttributeMaxDynamicSharedMemorySize, SMEM_BYTES);
        cudaFuncSetAttribute(k4, cudaFuncAttributeMaxDynamicSharedMemorySize, SMEM_BYTES);
        attr_done = true;
    }

    uint16_t *xh, *xl, *w1h, *w1l, *w3h, *w3l;
    cudaGetSymbolAddress((void**)&xh,  g_xh);  cudaGetSymbolAddress((void**)&xl,  g_xl);
    cudaGetSymbolAddress((void**)&w1h, g_w1h); cudaGetSymbolAddress((void**)&w1l, g_w1l);
    cudaGetSymbolAddress((void**)&w3h, g_w3h); cudaGetSymbolAddress((void**)&w3l, g_w3l);

    p_split<<<(BATCH * CIN * HW / 4 + 255) / 256, 256>>>(x, xh, xl, BATCH * CIN * HW / 4);
    p_split<<<(PMID * CIN / 4 + 255) / 256, 256>>>(w1, w1h, w1l, PMID * CIN / 4);
    p_split<<<(CIN * PMID / 4 + 255) / 256, 256>>>(w3, w3h, w3l, CIN * PMID / 4);
    p_wd<<<9 * 256, 256>>>(wd);

    k1<<<dim3(7, 2, BATCH), 256, SMEM_BYTES>>>();
    p_shuf9<<<BATCH * PMID, 256>>>(perm_d);
    k3<<<dim3(7, 2, BATCH), 256, SMEM_BYTES>>>();
    k4<<<dim3(7, 8, BATCH), 256, SMEM_BYTES>>>(x, perm_res, out);
}

// round 13
// speedup vs baseline: 1.4567x; 1.4567x over previous
#include <cuda_runtime.h>
#include <cuda_bf16.h>
#include <cstdint>

#define BATCH 32
#define HBATCH 16
#define CIN   1024
#define PMID  256
#define HW    784

// Pre-split operands (bf16 hi/lo)
__device__ uint16_t g_xh [BATCH * CIN * HW],  g_xl [BATCH * CIN * HW];
__device__ uint16_t g_w1h[PMID * CIN],        g_w1l[PMID * CIN];
__device__ uint16_t g_w3h[CIN * PMID],        g_w3l[CIN * PMID];
__device__ uint16_t g_wdh[9 * PMID * PMID],   g_wdl[9 * PMID * PMID];   // [tap][q][p]
__device__ uint16_t g_y1h[BATCH * PMID * HW], g_y1l[BATCH * PMID * HW];
// im2col: 9 tap-shifted shuffled copies, compact [tap][b*PMID+p][784]
__device__ uint16_t g_ysth[9 * BATCH * PMID * HW], g_ystl[9 * BATCH * PMID * HW];
__device__ uint16_t g_y2h[BATCH * PMID * HW], g_y2l[BATCH * PMID * HW];

// SMEM: 2 stages. A rows 80B (k32+8pad), B rows 240B (n112+8pad)
#define ASTRIDE 10240u
#define BSTRIDE 7680u
#define OFF_AL  20480u
#define OFF_BH  40960u
#define OFF_BL  56320u
#define SMEM_BYTES 71680

// ---------------------------------------------------------------------------
__device__ __forceinline__ void split_bf(float v, uint16_t& h, uint16_t& l) {
    __nv_bfloat16 bh = __float2bfloat16(v);
    float r = v - __bfloat162float(bh);
    h = __bfloat16_as_ushort(bh);
    l = __bfloat16_as_ushort(__float2bfloat16(r));
}
__device__ __forceinline__ uint32_t pack2(uint16_t a, uint16_t b) {
    return (uint32_t)a | ((uint32_t)b << 16);
}
__device__ __forceinline__ uint32_t smem_u32(const void* p) {
    uint32_t a;
    asm("{ .reg .u64 t; cvta.to.shared.u64 t, %1; cvt.u32.u64 %0, t; }" : "=r"(a) : "l"(p));
    return a;
}
__device__ __forceinline__ void cp16(uint32_t d, const void* s) {
    asm volatile("cp.async.ca.shared.global [%0], [%1], 16;" :: "r"(d), "l"(s));
}
#define CP_COMMIT() asm volatile("cp.async.commit_group;" ::: "memory")
#define CP_WAIT0()  asm volatile("cp.async.wait_group 0;" ::: "memory")

__device__ __forceinline__ void ldm_x4(uint32_t* r, uint32_t a) {
    asm volatile("ldmatrix.sync.aligned.m8n8.x4.shared.b16 {%0,%1,%2,%3}, [%4];"
        : "=r"(r[0]), "=r"(r[1]), "=r"(r[2]), "=r"(r[3]) : "r"(a));
}
__device__ __forceinline__ void ldm_x4t(uint32_t* r, uint32_t a) {
    asm volatile("ldmatrix.sync.aligned.m8n8.x4.trans.shared.b16 {%0,%1,%2,%3}, [%4];"
        : "=r"(r[0]), "=r"(r[1]), "=r"(r[2]), "=r"(r[3]) : "r"(a));
}
__device__ __forceinline__ void ldm_x2t(uint32_t* r, uint32_t a) {
    asm volatile("ldmatrix.sync.aligned.m8n8.x2.trans.shared.b16 {%0,%1}, [%2];"
        : "=r"(r[0]), "=r"(r[1]) : "r"(a));
}
__device__ __forceinline__ void mma_bf(float* d, const uint32_t* a,
                                       uint32_t b0, uint32_t b1) {
    asm volatile(
        "mma.sync.aligned.m16n8k16.row.col.f32.bf16.bf16.f32 "
        "{%0,%1,%2,%3}, {%4,%5,%6,%7}, {%8,%9}, {%0,%1,%2,%3};"
        : "+f"(d[0]), "+f"(d[1]), "+f"(d[2]), "+f"(d[3])
        : "r"(a[0]), "r"(a[1]), "r"(a[2]), "r"(a[3]), "r"(b0), "r"(b1));
}

// One BK=32 chunk; warp tile 32(M) x 56(N); split-bf16 x3 (hh, lh, hl).
__device__ __forceinline__ void compute_chunk32(
    uint32_t ah, uint32_t al, uint32_t bh, uint32_t bl,
    uint32_t aoff0, uint32_t aoff1, uint32_t boff, uint32_t boff6,
    float acc[2][7][4]) {
    #pragma unroll
    for (int s = 0; s < 2; s++) {
        uint32_t a_h[2][4], a_l[2][4];
        ldm_x4(a_h[0], ah + aoff0 + s * 32);
        ldm_x4(a_h[1], ah + aoff1 + s * 32);
        ldm_x4(a_l[0], al + aoff0 + s * 32);
        ldm_x4(a_l[1], al + aoff1 + s * 32);
        const uint32_t bstep = s * 3840;   // 16 k-rows x 240B
        #pragma unroll
        for (int j2 = 0; j2 < 3; j2++) {
            uint32_t rh[4], rl[4];
            ldm_x4t(rh, bh + boff + bstep + j2 * 32);
            ldm_x4t(rl, bl + boff + bstep + j2 * 32);
            #pragma unroll
            for (int jj = 0; jj < 2; jj++) {
                const int j = 2 * j2 + jj;
                #pragma unroll
                for (int i = 0; i < 2; i++) {
                    mma_bf(acc[i][j], a_h[i], rh[2*jj], rh[2*jj+1]);
                    mma_bf(acc[i][j], a_l[i], rh[2*jj], rh[2*jj+1]);
                    mma_bf(acc[i][j], a_h[i], rl[2*jj], rl[2*jj+1]);
                }
            }
        }
        {
            uint32_t rh[2], rl[2];
            ldm_x2t(rh, bh + boff6 + bstep);
            ldm_x2t(rl, bl + boff6 + bstep);
            #pragma unroll
            for (int i = 0; i < 2; i++) {
                mma_bf(acc[i][6], a_h[i], rh[0], rh[1]);
                mma_bf(acc[i][6], a_l[i], rh[0], rh[1]);
                mma_bf(acc[i][6], a_h[i], rl[0], rl[1]);
            }
        }
    }
}

// ---------------------------------------------------------------------------
// Prep kernels
// ---------------------------------------------------------------------------
__global__ __launch_bounds__(256) void p_split(const float* __restrict__ in,
                                               uint16_t* __restrict__ oh,
                                               uint16_t* __restrict__ ol, int n4) {
    int i = blockIdx.x * 256 + threadIdx.x;
    if (i >= n4) return;
    float4 v = ((const float4*)in)[i];
    uint16_t h0,l0,h1,l1,h2,l2,h3,l3;
    split_bf(v.x,h0,l0); split_bf(v.y,h1,l1); split_bf(v.z,h2,l2); split_bf(v.w,h3,l3);
    ((uint2*)oh)[i] = make_uint2(pack2(h0,h1), pack2(h2,h3));
    ((uint2*)ol)[i] = make_uint2(pack2(l0,l1), pack2(l2,l3));
}

__global__ __launch_bounds__(256) void p_wd(const float* __restrict__ wd) {
    int e = blockIdx.x * 256 + threadIdx.x;   // e = tap*65536 + q*256 + p
    int p = e & 255, q = (e >> 8) & 255, tap = e >> 16;
    float v = wd[q * 2304 + p * 9 + tap];
    uint16_t h, l; split_bf(v, h, l);
    g_wdh[e] = h; g_wdl[e] = l;
}

// shuffle + im2col: for each (b,p) produce 9 tap-shifted rows of 784
__global__ __launch_bounds__(256) void p_shuf9(const int* __restrict__ perm, int bp0) {
    __shared__ int sperm[HW];
    __shared__ uint16_t syh[HW], syl[HW];
    const int bp = blockIdx.x + bp0, p = bp & (PMID - 1);
    const int tid = threadIdx.x;
    for (int t = tid; t < HW; t += 256) {
        sperm[t] = perm[(size_t)p * HW + t];
        syh[t] = g_y1h[(size_t)bp * HW + t];
        syl[t] = g_y1l[(size_t)bp * HW + t];
    }
    __syncthreads();
    #pragma unroll
    for (int tap = 0; tap < 9; tap++) {
        const int dy = tap / 3 - 1, dx = tap % 3 - 1;
        uint16_t* dh = g_ysth + ((size_t)tap * (BATCH * PMID) + bp) * HW;
        uint16_t* dl = g_ystl + ((size_t)tap * (BATCH * PMID) + bp) * HW;
        for (int hw = tid; hw < HW; hw += 256) {
            int h = hw / 28 + dy, w = hw % 28 + dx;
            uint16_t vh = 0, vl = 0;
            if ((unsigned)h < 28u && (unsigned)w < 28u) {
                int j = sperm[h * 28 + w];
                vh = syh[j]; vl = syl[j];
            }
            dh[hw] = vh; dl[hw] = vl;
        }
    }
}

// ---------------------------------------------------------------------------
// Common per-kernel decls: 256 threads, 8 warps = 4(wm) x 2(wn), warp 32x56.
// ---------------------------------------------------------------------------
#define PIPE_DECLS()                                                           \
    extern __shared__ uint16_t sm[];                                           \
    const uint32_t sb = smem_u32(sm);                                          \
    const int tid = threadIdx.x, lane = tid & 31, warp = tid >> 5;             \
    const int wm = warp >> 1, wn = warp & 1;                                   \
    const int ar = tid >> 1, ac = (tid & 1) << 4;                              \
    const int bkc = tid / 7, bch = (tid % 7) << 4;                             \
    const uint32_t aoff0 = ((wm * 32 + (lane & 15)) * 40 + ((lane >> 4) << 3)) * 2;      \
    const uint32_t aoff1 = ((wm * 32 + 16 + (lane & 15)) * 40 + ((lane >> 4) << 3)) * 2; \
    const uint32_t boff  = ((lane & 15) * 120 + wn * 56 + ((lane >> 4) << 3)) * 2;       \
    const uint32_t boff6 = ((lane & 15) * 120 + wn * 56 + 48) * 2;             \
    float acc[2][7][4] = {};

// ---------------------------------------------------------------------------
// K1: y1 = relu(w1 @ x). M=256, K=1024, N=784. Tile 128x112, BK=32, 256 thr.
// ---------------------------------------------------------------------------
__global__ __launch_bounds__(256, 2) void k1(int b0) {
    const int b = blockIdx.z + b0, m0 = blockIdx.y * 128, n0 = blockIdx.x * 112;
    const uint16_t* xh = g_xh + (size_t)b * CIN * HW;
    const uint16_t* xl = g_xl + (size_t)b * CIN * HW;
    PIPE_DECLS();

#define K1_ISSUE(k0, st) do {                                                  \
    cp16(sb + (st) * ASTRIDE + (ar * 40 + ac) * 2,                             \
         g_w1h + (size_t)(m0 + ar) * CIN + (k0) + ac);                         \
    cp16(sb + (st) * ASTRIDE + (ar * 40 + ac + 8) * 2,                         \
         g_w1h + (size_t)(m0 + ar) * CIN + (k0) + ac + 8);                     \
    cp16(sb + OFF_AL + (st) * ASTRIDE + (ar * 40 + ac) * 2,                    \
         g_w1l + (size_t)(m0 + ar) * CIN + (k0) + ac);                         \
    cp16(sb + OFF_AL + (st) * ASTRIDE + (ar * 40 + ac + 8) * 2,                \
         g_w1l + (size_t)(m0 + ar) * CIN + (k0) + ac + 8);                     \
    if (tid < 224) {                                                           \
        cp16(sb + OFF_BH + (st) * BSTRIDE + (bkc * 120 + bch) * 2,             \
             xh + (size_t)((k0) + bkc) * HW + n0 + bch);                       \
        cp16(sb + OFF_BH + (st) * BSTRIDE + (bkc * 120 + bch + 8) * 2,         \
             xh + (size_t)((k0) + bkc) * HW + n0 + bch + 8);                   \
        cp16(sb + OFF_BL + (st) * BSTRIDE + (bkc * 120 + bch) * 2,             \
             xl + (size_t)((k0) + bkc) * HW + n0 + bch);                       \
        cp16(sb + OFF_BL + (st) * BSTRIDE + (bkc * 120 + bch + 8) * 2,         \
             xl + (size_t)((k0) + bkc) * HW + n0 + bch + 8);                   \
    }                                                                          \
    CP_COMMIT(); } while (0)

    K1_ISSUE(0, 0);
    for (int c = 0; c < 32; c++) {
        const int s = c & 1;
        CP_WAIT0(); __syncthreads();
        if (c + 1 < 32) K1_ISSUE((c + 1) * 32, s ^ 1);
        compute_chunk32(sb + s * ASTRIDE, sb + OFF_AL + s * ASTRIDE,
                        sb + OFF_BH + s * BSTRIDE, sb + OFF_BL + s * BSTRIDE,
                        aoff0, aoff1, boff, boff6, acc);
    }
#undef K1_ISSUE

    const int r0 = lane >> 2, c2 = (lane & 3) << 1;
    #pragma unroll
    for (int i = 0; i < 2; i++)
        #pragma unroll
        for (int rp = 0; rp < 2; rp++) {
            int m = m0 + wm * 32 + i * 16 + r0 + rp * 8;
            size_t base = (size_t)(b * PMID + m) * HW + n0;
            #pragma unroll
            for (int j = 0; j < 7; j++) {
                int col = wn * 56 + j * 8 + c2;
                float v0 = fmaxf(acc[i][j][rp * 2], 0.f);
                float v1 = fmaxf(acc[i][j][rp * 2 + 1], 0.f);
                uint16_t h0,l0,h1,l1; split_bf(v0,h0,l0); split_bf(v1,h1,l1);
                *(uint32_t*)&g_y1h[base + col] = pack2(h0, h1);
                *(uint32_t*)&g_y1l[base + col] = pack2(l0, l1);
            }
        }
}

// ---------------------------------------------------------------------------
// K3: y2 = relu(conv3x3). 72 chunks = 9 taps x 8 p-chunks, pure cp.async GEMM.
// ---------------------------------------------------------------------------
__global__ __launch_bounds__(256, 2) void k3(int b0) {
    const int b = blockIdx.z + b0, q0 = blockIdx.y * 128, n0 = blockIdx.x * 112;
    PIPE_DECLS();

#define K3_ISSUE(cc, st) do {                                                  \
    int tap_ = (cc) >> 3, p0_ = ((cc) & 7) << 5;                               \
    const uint16_t* wah = g_wdh + (size_t)tap_ * 65536 + (size_t)(q0 + ar) * 256 + p0_; \
    const uint16_t* wal = g_wdl + (size_t)tap_ * 65536 + (size_t)(q0 + ar) * 256 + p0_; \
    cp16(sb + (st) * ASTRIDE + (ar * 40 + ac) * 2,           wah + ac);        \
    cp16(sb + (st) * ASTRIDE + (ar * 40 + ac + 8) * 2,       wah + ac + 8);    \
    cp16(sb + OFF_AL + (st) * ASTRIDE + (ar * 40 + ac) * 2,     wal + ac);     \
    cp16(sb + OFF_AL + (st) * ASTRIDE + (ar * 40 + ac + 8) * 2, wal + ac + 8); \
    if (tid < 224) {                                                           \
        size_t brow = ((size_t)tap_ * (BATCH * PMID) + (size_t)b * PMID + p0_ + bkc) * HW + n0; \
        cp16(sb + OFF_BH + (st) * BSTRIDE + (bkc * 120 + bch) * 2,     g_ysth + brow + bch);     \
        cp16(sb + OFF_BH + (st) * BSTRIDE + (bkc * 120 + bch + 8) * 2, g_ysth + brow + bch + 8); \
        cp16(sb + OFF_BL + (st) * BSTRIDE + (bkc * 120 + bch) * 2,     g_ystl + brow + bch);     \
        cp16(sb + OFF_BL + (st) * BSTRIDE + (bkc * 120 + bch + 8) * 2, g_ystl + brow + bch + 8); \
    }                                                                          \
    CP_COMMIT(); } while (0)

    K3_ISSUE(0, 0);
    for (int c = 0; c < 72; c++) {
        const int s = c & 1;
        CP_WAIT0(); __syncthreads();
        if (c + 1 < 72) K3_ISSUE(c + 1, s ^ 1);
        compute_chunk32(sb + s * ASTRIDE, sb + OFF_AL + s * ASTRIDE,
                        sb + OFF_BH + s * BSTRIDE, sb + OFF_BL + s * BSTRIDE,
                        aoff0, aoff1, boff, boff6, acc);
    }
#undef K3_ISSUE

    const int r0 = lane >> 2, c2 = (lane & 3) << 1;
    #pragma unroll
    for (int i = 0; i < 2; i++)
        #pragma unroll
        for (int rp = 0; rp < 2; rp++) {
            int q = q0 + wm * 32 + i * 16 + r0 + rp * 8;
            size_t base = (size_t)(b * PMID + q) * HW + n0;
            #pragma unroll
            for (int j = 0; j < 7; j++) {
                int col = wn * 56 + j * 8 + c2;
                float v0 = fmaxf(acc[i][j][rp * 2], 0.f);
                float v1 = fmaxf(acc[i][j][rp * 2 + 1], 0.f);
                uint16_t h0,l0,h1,l1; split_bf(v0,h0,l0); split_bf(v1,h1,l1);
                *(uint32_t*)&g_y2h[base + col] = pack2(h0, h1);
                *(uint32_t*)&g_y2l[base + col] = pack2(l0, l1);
            }
        }
}

// ---------------------------------------------------------------------------
// K4: out = relu(w3 @ y2 + shuffled residual). M=1024, K=256.
// ---------------------------------------------------------------------------
__global__ __launch_bounds__(256, 2) void k4(const float* __restrict__ x,
                                             const int* __restrict__ perm_res,
                                             float* __restrict__ out, int b0) {
    const int b = blockIdx.z + b0, m0 = blockIdx.y * 128, n0 = blockIdx.x * 112;
    const uint16_t* yh = g_y2h + (size_t)b * PMID * HW;
    const uint16_t* yl = g_y2l + (size_t)b * PMID * HW;
    PIPE_DECLS();

#define K4_ISSUE(k0, st) do {                                                  \
    cp16(sb + (st) * ASTRIDE + (ar * 40 + ac) * 2,                             \
         g_w3h + (size_t)(m0 + ar) * PMID + (k0) + ac);                        \
    cp16(sb + (st) * ASTRIDE + (ar * 40 + ac + 8) * 2,                         \
         g_w3h + (size_t)(m0 + ar) * PMID + (k0) + ac + 8);                    \
    cp16(sb + OFF_AL + (st) * ASTRIDE + (ar * 40 + ac) * 2,                    \
         g_w3l + (size_t)(m0 + ar) * PMID + (k0) + ac);                        \
    cp16(sb + OFF_AL + (st) * ASTRIDE + (ar * 40 + ac + 8) * 2,                \
         g_w3l + (size_t)(m0 + ar) * PMID + (k0) + ac + 8);                    \
    if (tid < 224) {                                                           \
        cp16(sb + OFF_BH + (st) * BSTRIDE + (bkc * 120 + bch) * 2,             \
             yh + (size_t)((k0) + bkc) * HW + n0 + bch);                       \
        cp16(sb + OFF_BH + (st) * BSTRIDE + (bkc * 120 + bch + 8) * 2,         \
             yh + (size_t)((k0) + bkc) * HW + n0 + bch + 8);                   \
        cp16(sb + OFF_BL + (st) * BSTRIDE + (bkc * 120 + bch) * 2,             \
             yl + (size_t)((k0) + bkc) * HW + n0 + bch);                       \
        cp16(sb + OFF_BL + (st) * BSTRIDE + (bkc * 120 + bch + 8) * 2,         \
             yl + (size_t)((k0) + bkc) * HW + n0 + bch + 8);                   \
    }                                                                          \
    CP_COMMIT(); } while (0)

    K4_ISSUE(0, 0);
    for (int c = 0; c < 8; c++) {
        const int s = c & 1;
        CP_WAIT0(); __syncthreads();
        if (c + 1 < 8) K4_ISSUE((c + 1) * 32, s ^ 1);
        compute_chunk32(sb + s * ASTRIDE, sb + OFF_AL + s * ASTRIDE,
                        sb + OFF_BH + s * BSTRIDE, sb + OFF_BL + s * BSTRIDE,
                        aoff0, aoff1, boff, boff6, acc);
    }
#undef K4_ISSUE

    const int r0 = lane >> 2, c2 = (lane & 3) << 1;
    #pragma unroll
    for (int i = 0; i < 2; i++)
        #pragma unroll
        for (int rp = 0; rp < 2; rp++) {
            int m = m0 + wm * 32 + i * 16 + r0 + rp * 8;
            const int*   pr  = perm_res + (size_t)m * HW + n0;
            const float* xr  = x   + (size_t)(b * CIN + m) * HW;
            float*       dst = out + (size_t)(b * CIN + m) * HW + n0;
            #pragma unroll
            for (int j = 0; j < 7; j++) {
                int col = wn * 56 + j * 8 + c2;
                float v0 = acc[i][j][rp * 2]     + xr[pr[col]];
                float v1 = acc[i][j][rp * 2 + 1] + xr[pr[col + 1]];
                *(float2*)&dst[col] = make_float2(fmaxf(v0, 0.f), fmaxf(v1, 0.f));
            }
        }
}

// ---------------------------------------------------------------------------
extern "C" void kernel_launch(void* const* d_in, const int* in_sizes, int n_in,
                              void* d_out, int out_size) {
    const float* x        = (const float*)d_in[0];
    const float* w1       = (const float*)d_in[1];
    const float* wd       = (const float*)d_in[2];
    const float* w3       = (const float*)d_in[3];
    const int*   perm_d   = (const int*)d_in[4];
    const int*   perm_res = (const int*)d_in[5];
    float* out = (float*)d_out;
    (void)in_sizes; (void)n_in; (void)out_size;

    static bool init_done = false;
    static cudaStream_t s2 = 0;
    static cudaEvent_t evW = 0, evEnd = 0;
    if (!init_done) {
        cudaFuncSetAttribute(k1, cudaFuncAttributeMaxDynamicSharedMemorySize, SMEM_BYTES);
        cudaFuncSetAttribute(k3, cudaFuncAttributeMaxDynamicSharedMemorySize, SMEM_BYTES);
        cudaFuncSetAttribute(k4, cudaFuncAttributeMaxDynamicSharedMemorySize, SMEM_BYTES);
        cudaStreamCreateWithFlags(&s2, cudaStreamNonBlocking);
        cudaEventCreateWithFlags(&evW, cudaEventDisableTiming);
        cudaEventCreateWithFlags(&evEnd, cudaEventDisableTiming);
        init_done = true;
    }

    uint16_t *xh, *xl, *w1h, *w1l, *w3h, *w3l;
    cudaGetSymbolAddress((void**)&xh,  g_xh);  cudaGetSymbolAddress((void**)&xl,  g_xl);
    cudaGetSymbolAddress((void**)&w1h, g_w1h); cudaGetSymbolAddress((void**)&w1l, g_w1l);
    cudaGetSymbolAddress((void**)&w3h, g_w3h); cudaGetSymbolAddress((void**)&w3l, g_w3l);

    const int XHALF  = HBATCH * CIN * HW;        // elements per batch-half
    const int XH4    = XHALF / 4;

    // Weight prep on the main (captured) stream
    p_split<<<(PMID * CIN / 4 + 255) / 256, 256>>>(w1, w1h, w1l, PMID * CIN / 4);
    p_split<<<(CIN * PMID / 4 + 255) / 256, 256>>>(w3, w3h, w3l, CIN * PMID / 4);
    p_wd<<<9 * 256, 256>>>(wd);
    cudaEventRecord(evW, 0);

    // Half 1 chain on s2 (forked from captured stream via event)
    cudaStreamWaitEvent(s2, evW, 0);
    p_split<<<(XH4 + 255) / 256, 256, 0, s2>>>(x + XHALF, xh + XHALF, xl + XHALF, XH4);
    k1<<<dim3(7, 2, HBATCH), 256, SMEM_BYTES, s2>>>(HBATCH);
    p_shuf9<<<HBATCH * PMID, 256, 0, s2>>>(perm_d, HBATCH * PMID);
    k3<<<dim3(7, 2, HBATCH), 256, SMEM_BYTES, s2>>>(HBATCH);
    k4<<<dim3(7, 8, HBATCH), 256, SMEM_BYTES, s2>>>(x, perm_res, out, HBATCH);
    cudaEventRecord(evEnd, s2);

    // Half 0 chain on the main stream
    p_split<<<(XH4 + 255) / 256, 256>>>(x, xh, xl, XH4);
    k1<<<dim3(7, 2, HBATCH), 256, SMEM_BYTES>>>(0);
    p_shuf9<<<HBATCH * PMID, 256>>>(perm_d, 0);
    k3<<<dim3(7, 2, HBATCH), 256, SMEM_BYTES>>>(0);
    k4<<<dim3(7, 8, HBATCH), 256, SMEM_BYTES>>>(x, perm_res, out, 0);

    // Join
    cudaStreamWaitEvent(0, evEnd, 0);
}